// round 3
// baseline (speedup 1.0000x reference)
#include <cuda_runtime.h>
#include <math.h>

#define WD 16384
constexpr int Bsz   = 8;
constexpr int C     = 256;   // CIN == HID
constexpr int HEADS = 8;
constexpr int HD    = 32;
constexpr int KW    = 31;
constexpr int PAD   = 15;

// ---- scratch (device globals: allocation-free) ----
__device__ float g_qWk[C * HEADS];                       // [D][h]
__device__ float g_qb[HEADS];
__device__ float g_cexp[(size_t)Bsz * HEADS * WD];       // 4 MB
__device__ float g_vc [(size_t)Bsz * C * WD];            // 128 MB
__device__ float g_u  [(size_t)Bsz * C * WD];            // 128 MB

// ---------------------------------------------------------------------------
// K1: normalized query, qWk = q_hat @ Wk (per head), qb = q_hat . Wk_bias
// 1 block, 256 threads. thread t == channel D for qWk; warp h for norms.
// ---------------------------------------------------------------------------
__global__ void k_prep(const float* __restrict__ query,
                       const float* __restrict__ Wk,
                       const float* __restrict__ Wk_bias)
{
    __shared__ float qn[C];
    int t = threadIdx.x;            // 0..255
    float qv = query[t];
    // per-head (per-warp, HD==32) L2 norm
    float ss = qv * qv;
    #pragma unroll
    for (int o = 16; o > 0; o >>= 1) ss += __shfl_xor_sync(0xffffffffu, ss, o);
    float nrm = sqrtf(ss) + 1e-6f;
    float qnv = (qv / nrm) * 0.17677669529663687f;  // 1/sqrt(32)
    qn[t] = qnv;
    // qb[h] = sum_e qn * bias
    float bb = qnv * Wk_bias[t];
    #pragma unroll
    for (int o = 16; o > 0; o >>= 1) bb += __shfl_xor_sync(0xffffffffu, bb, o);
    if ((t & 31) == 0) g_qb[t >> 5] = bb;
    __syncthreads();
    // qWk[D][h]
    #pragma unroll
    for (int h = 0; h < HEADS; h++) {
        float acc = 0.f;
        #pragma unroll
        for (int e = 0; e < HD; e++)
            acc += qn[h * HD + e] * Wk[t * C + h * HD + e];
        g_qWk[t * HEADS + h] = acc;
    }
}

// ---------------------------------------------------------------------------
// K2: cost_exp[b][h][w] = exp( sum_D x[b][D][w] * qWk[D][h] + qb[h] )
// grid (WD/256, B), 256 threads, thread == w
// ---------------------------------------------------------------------------
__global__ __launch_bounds__(256)
void k_cost(const float* __restrict__ x)
{
    __shared__ float sQ[C * HEADS];
    __shared__ float sqb[HEADS];
    int t = threadIdx.x;
    for (int i = t; i < C * HEADS; i += 256) sQ[i] = g_qWk[i];
    if (t < HEADS) sqb[t] = g_qb[t];
    __syncthreads();

    int b = blockIdx.y;
    int w = blockIdx.x * 256 + t;
    const float* xp = x + ((size_t)b * C) * WD + w;

    float acc[HEADS];
    #pragma unroll
    for (int h = 0; h < HEADS; h++) acc[h] = sqb[h];

    for (int d = 0; d < C; d++) {
        float xv = xp[(size_t)d * WD];
        #pragma unroll
        for (int h = 0; h < HEADS; h++) acc[h] += xv * sQ[d * HEADS + h];
    }
    #pragma unroll
    for (int h = 0; h < HEADS; h++)
        g_cexp[((size_t)(b * HEADS + h)) * WD + w] = expf(acc[h]);
}

// ---------------------------------------------------------------------------
// K3 / K5: SGEMM  Out[b][o][w] = sum_d Wt[o][d] * In[b][d][w]  (+epilogue)
// MODE 0: In = x (param), Out = g_vc, epilogue *(cexp) after +bias
// MODE 1: In = g_u,       Out = param, epilogue +bias
// BM=64 x BN=128 x BK=16, 256 threads, 4x8 regtile.
// ---------------------------------------------------------------------------
constexpr int BM = 64, BN = 128, BK = 16;

template <int MODE>
__global__ __launch_bounds__(256)
void k_gemm(const float* __restrict__ Wt,
            const float* __restrict__ bias,
            const float* __restrict__ InP,
            float* __restrict__ OutP)
{
    __shared__ float As[BM][BK];    // [o][k]  (reads are warp-broadcast)
    __shared__ float Bs[BK][BN];    // [k][w]  (reads are consecutive-lane)

    const float* In  = (MODE == 0) ? InP : g_u;
    float*       Out = (MODE == 0) ? g_vc : OutP;

    int t  = threadIdx.x;
    int tx = t & 15;        // w group
    int ty = t >> 4;        // o group
    int b  = blockIdx.z;
    int o0 = blockIdx.y * BM;
    int w0 = blockIdx.x * BN;

    float acc[4][8];
    #pragma unroll
    for (int i = 0; i < 4; i++)
        #pragma unroll
        for (int j = 0; j < 8; j++) acc[i][j] = 0.f;

    // load assignments
    int ao = t >> 2;             // 0..63   (A row)
    int ak = (t & 3) * 4;        // 0/4/8/12
    int bj = t >> 4;             // 0..15   (B row)
    int bc = (t & 15) * 8;       // 0..120

    const float* Aptr = Wt + (size_t)(o0 + ao) * C + ak;
    const float* Bptr = In + ((size_t)(b * C + bj)) * WD + w0 + bc;

    for (int k0 = 0; k0 < C; k0 += BK) {
        float4 av = *(const float4*)(Aptr + k0);
        *(float4*)&As[ao][ak] = av;
        float4 b0 = *(const float4*)(Bptr + (size_t)k0 * WD);
        float4 b1 = *(const float4*)(Bptr + (size_t)k0 * WD + 4);
        *(float4*)&Bs[bj][bc]     = b0;
        *(float4*)&Bs[bj][bc + 4] = b1;
        __syncthreads();

        #pragma unroll
        for (int k = 0; k < BK; k++) {
            float a[4], bb[8];
            #pragma unroll
            for (int i = 0; i < 4; i++) a[i] = As[ty + 16 * i][k];
            #pragma unroll
            for (int j = 0; j < 8; j++) bb[j] = Bs[k][tx + 16 * j];
            #pragma unroll
            for (int i = 0; i < 4; i++)
                #pragma unroll
                for (int j = 0; j < 8; j++) acc[i][j] += a[i] * bb[j];
        }
        __syncthreads();
    }

    // epilogue
    #pragma unroll
    for (int i = 0; i < 4; i++) {
        int o = o0 + ty + 16 * i;
        float bv = bias[o];
        float* op = Out + ((size_t)(b * C + o)) * WD + w0;
        if (MODE == 0) {
            int h = o >> 5;
            const float* ce = g_cexp + ((size_t)(b * HEADS + h)) * WD + w0;
            #pragma unroll
            for (int j = 0; j < 8; j++) {
                int w = tx + 16 * j;
                op[w] = (acc[i][j] + bv) * ce[w];
            }
        } else {
            #pragma unroll
            for (int j = 0; j < 8; j++) {
                int w = tx + 16 * j;
                op[w] = acc[i][j] + bv;
            }
        }
    }
}

// ---------------------------------------------------------------------------
// K4: depthwise K=31 conv (cross-correlation, zero pad 15) + divide:
//     u[b][c][w] = (sum_k rexp[h][k]*vc[c][w+k-15]) / (sum_k rexp[h][k]*cexp[h][w+k-15])
// grid (WD/256, C, B), 256 threads
// ---------------------------------------------------------------------------
__global__ __launch_bounds__(256)
void k_conv(const float* __restrict__ rpe)
{
    __shared__ float svc[256 + 2 * PAD];
    __shared__ float sce[256 + 2 * PAD];
    __shared__ float srk[KW];

    int t  = threadIdx.x;
    int c  = blockIdx.y;
    int b  = blockIdx.z;
    int w0 = blockIdx.x * 256;
    int h  = c >> 5;

    if (t < KW) srk[t] = expf(rpe[h * KW + t]);

    const float* vcrow = g_vc   + ((size_t)(b * C + c)) * WD;
    const float* cerow = g_cexp + ((size_t)(b * HEADS + h)) * WD;
    for (int idx = t; idx < 256 + 2 * PAD; idx += 256) {
        int gw = w0 - PAD + idx;
        bool ok = (gw >= 0) && (gw < WD);
        svc[idx] = ok ? vcrow[gw] : 0.f;
        sce[idx] = ok ? cerow[gw] : 0.f;
    }
    __syncthreads();

    float sv = 0.f, sc = 0.f;
    #pragma unroll
    for (int k = 0; k < KW; k++) {
        float r = srk[k];
        sv += r * svc[t + k];
        sc += r * sce[t + k];
    }
    g_u[((size_t)(b * C + c)) * WD + w0 + t] = sv / sc;
}

// ---------------------------------------------------------------------------
extern "C" void kernel_launch(void* const* d_in, const int* in_sizes, int n_in,
                              void* d_out, int out_size)
{
    (void)in_sizes; (void)n_in; (void)out_size;
    const float* x     = (const float*)d_in[0];
    const float* query = (const float*)d_in[1];
    const float* Wk    = (const float*)d_in[2];
    const float* Wkb   = (const float*)d_in[3];
    const float* rpe   = (const float*)d_in[4];
    const float* Wv    = (const float*)d_in[5];
    const float* bv    = (const float*)d_in[6];
    const float* Wo    = (const float*)d_in[7];
    const float* bo    = (const float*)d_in[8];
    float* out = (float*)d_out;

    k_prep<<<1, 256>>>(query, Wk, Wkb);
    k_cost<<<dim3(WD / 256, Bsz), 256>>>(x);
    k_gemm<0><<<dim3(WD / BN, C / BM, Bsz), 256>>>(Wv, bv, x, nullptr);
    k_conv<<<dim3(WD / 256, C, Bsz), 256>>>(rpe);
    k_gemm<1><<<dim3(WD / BN, C / BM, Bsz), 256>>>(Wo, bo, nullptr, out);
}

// round 4
// speedup vs baseline: 1.6324x; 1.6324x over previous
#include <cuda_runtime.h>
#include <math.h>

#define WD 16384
constexpr int Bsz   = 8;
constexpr int C     = 256;   // CIN == HID
constexpr int HEADS = 8;
constexpr int HD    = 32;
constexpr int KW    = 31;
constexpr int PAD   = 15;

// ---- scratch (device globals: allocation-free) ----
__device__ float g_qWk[C * HEADS];                       // [D][h]
__device__ float g_qb[HEADS];
__device__ float g_cexp[(size_t)Bsz * HEADS * WD];       // 4 MB
__device__ float g_srec[(size_t)Bsz * HEADS * WD];       // 4 MB  (1 / sum_c)
__device__ float g_vc [(size_t)Bsz * C * WD];            // 128 MB
__device__ float g_u  [(size_t)Bsz * C * WD];            // 128 MB

// ---------------------------------------------------------------------------
// K1: normalized query, qWk = q_hat @ Wk (per head), qb = q_hat . Wk_bias
// ---------------------------------------------------------------------------
__global__ void k_prep(const float* __restrict__ query,
                       const float* __restrict__ Wk,
                       const float* __restrict__ Wk_bias)
{
    __shared__ float qn[C];
    int t = threadIdx.x;            // 0..255
    float qv = query[t];
    float ss = qv * qv;
    #pragma unroll
    for (int o = 16; o > 0; o >>= 1) ss += __shfl_xor_sync(0xffffffffu, ss, o);
    float nrm = sqrtf(ss) + 1e-6f;
    float qnv = (qv / nrm) * 0.17677669529663687f;  // 1/sqrt(32)
    qn[t] = qnv;
    float bb = qnv * Wk_bias[t];
    #pragma unroll
    for (int o = 16; o > 0; o >>= 1) bb += __shfl_xor_sync(0xffffffffu, bb, o);
    if ((t & 31) == 0) g_qb[t >> 5] = bb;
    __syncthreads();
    #pragma unroll
    for (int h = 0; h < HEADS; h++) {
        float acc = 0.f;
        #pragma unroll
        for (int e = 0; e < HD; e++)
            acc += qn[h * HD + e] * Wk[t * C + h * HD + e];
        g_qWk[t * HEADS + h] = acc;
    }
}

// ---------------------------------------------------------------------------
// K2: cost_exp[b][h][w] = exp( sum_D x[b][D][w] * qWk[D][h] + qb[h] )
// ---------------------------------------------------------------------------
__global__ __launch_bounds__(256)
void k_cost(const float* __restrict__ x)
{
    __shared__ float sQ[C * HEADS];
    __shared__ float sqb[HEADS];
    int t = threadIdx.x;
    for (int i = t; i < C * HEADS; i += 256) sQ[i] = g_qWk[i];
    if (t < HEADS) sqb[t] = g_qb[t];
    __syncthreads();

    int b = blockIdx.y;
    int w = blockIdx.x * 256 + t;
    const float* xp = x + ((size_t)b * C) * WD + w;

    float acc[HEADS];
    #pragma unroll
    for (int h = 0; h < HEADS; h++) acc[h] = sqb[h];

    for (int d = 0; d < C; d++) {
        float xv = xp[(size_t)d * WD];
        #pragma unroll
        for (int h = 0; h < HEADS; h++) acc[h] += xv * sQ[d * HEADS + h];
    }
    #pragma unroll
    for (int h = 0; h < HEADS; h++)
        g_cexp[((size_t)(b * HEADS + h)) * WD + w] = expf(acc[h]);
}

// ---------------------------------------------------------------------------
// K3 / K5: SGEMM  Out[b][o][w] = sum_d Wt[o][d] * In[b][d][w]  (+epilogue)
// 128x128x8, 256 threads, 8x8 regtile, double-buffered smem.
// MODE 0: In = x (param), Out = g_vc, epilogue (acc+bias)*cexp
// MODE 1: In = g_u,       Out = param, epilogue acc+bias
// ---------------------------------------------------------------------------
constexpr int BM = 128, BN = 128, BK = 8;
constexpr int ASTR = BM + 4;    // padded A row stride (132 floats = 33*16B, keeps 16B align)

template <int MODE>
__global__ __launch_bounds__(256, 2)
void k_gemm(const float* __restrict__ Wt,
            const float* __restrict__ bias,
            const float* __restrict__ InP,
            float* __restrict__ OutP)
{
    __shared__ float As[2][BK][ASTR];   // transposed: As[k][m]
    __shared__ float Bs[2][BK][BN];     // Bs[k][n]

    const float* In  = (MODE == 0) ? InP : g_u;
    float*       Out = (MODE == 0) ? g_vc : OutP;

    int t  = threadIdx.x;
    int tx = t & 15;                // n quad
    int ty = t >> 4;                // m quad
    int b  = blockIdx.z;
    int o0 = blockIdx.y * BM;
    int w0 = blockIdx.x * BN;

    // global load assignments
    int ar = t >> 1;                // A row (o)  0..127
    int ak = (t & 1) * 4;           // A k        0 or 4
    int br = t >> 5;                // B row (k)  0..7
    int bc = (t & 31) * 4;          // B col      0..124

    const float* Ap = Wt + (size_t)(o0 + ar) * C + ak;
    const float* Bp = In + ((size_t)b * C + br) * WD + w0 + bc;

    // prologue: tile 0
    float4 aR = *(const float4*)Ap;
    float4 bR = *(const float4*)Bp;
    As[0][ak + 0][ar] = aR.x; As[0][ak + 1][ar] = aR.y;
    As[0][ak + 2][ar] = aR.z; As[0][ak + 3][ar] = aR.w;
    *(float4*)&Bs[0][br][bc] = bR;
    __syncthreads();

    float acc[8][8];
    #pragma unroll
    for (int i = 0; i < 8; i++)
        #pragma unroll
        for (int j = 0; j < 8; j++) acc[i][j] = 0.f;

    int buf = 0;
    for (int k0 = 0; k0 < C; k0 += BK) {
        bool more = (k0 + BK) < C;
        if (more) {
            aR = *(const float4*)(Ap + k0 + BK);
            bR = *(const float4*)(Bp + (size_t)(k0 + BK) * WD);
        }
        #pragma unroll
        for (int k = 0; k < BK; k++) {
            float4 a0 = *(const float4*)&As[buf][k][ty * 4];
            float4 a1 = *(const float4*)&As[buf][k][64 + ty * 4];
            float4 b0 = *(const float4*)&Bs[buf][k][tx * 4];
            float4 b1 = *(const float4*)&Bs[buf][k][64 + tx * 4];
            float av[8] = {a0.x, a0.y, a0.z, a0.w, a1.x, a1.y, a1.z, a1.w};
            float bv[8] = {b0.x, b0.y, b0.z, b0.w, b1.x, b1.y, b1.z, b1.w};
            #pragma unroll
            for (int i = 0; i < 8; i++)
                #pragma unroll
                for (int j = 0; j < 8; j++) acc[i][j] += av[i] * bv[j];
        }
        if (more) {
            int nb = buf ^ 1;
            As[nb][ak + 0][ar] = aR.x; As[nb][ak + 1][ar] = aR.y;
            As[nb][ak + 2][ar] = aR.z; As[nb][ak + 3][ar] = aR.w;
            *(float4*)&Bs[nb][br][bc] = bR;
            __syncthreads();
            buf = nb;
        }
    }

    // epilogue: rows o = o0 + {ty*4+i, 64+ty*4+i}, cols w = w0 + {tx*4+j, 64+tx*4+j}
    #pragma unroll
    for (int g = 0; g < 2; g++) {
        #pragma unroll
        for (int i = 0; i < 4; i++) {
            int o = o0 + g * 64 + ty * 4 + i;
            float bv = bias[o];
            float* op = Out + ((size_t)(b * C + o)) * WD + w0;
            if (MODE == 0) {
                int h = o >> 5;
                const float* ce = g_cexp + ((size_t)(b * HEADS + h)) * WD + w0;
                float4 c0 = *(const float4*)(ce + tx * 4);
                float4 c1 = *(const float4*)(ce + 64 + tx * 4);
                float4 r0, r1;
                r0.x = (acc[g*4+i][0] + bv) * c0.x; r0.y = (acc[g*4+i][1] + bv) * c0.y;
                r0.z = (acc[g*4+i][2] + bv) * c0.z; r0.w = (acc[g*4+i][3] + bv) * c0.w;
                r1.x = (acc[g*4+i][4] + bv) * c1.x; r1.y = (acc[g*4+i][5] + bv) * c1.y;
                r1.z = (acc[g*4+i][6] + bv) * c1.z; r1.w = (acc[g*4+i][7] + bv) * c1.w;
                *(float4*)(op + tx * 4)      = r0;
                *(float4*)(op + 64 + tx * 4) = r1;
            } else {
                float4 r0, r1;
                r0.x = acc[g*4+i][0] + bv; r0.y = acc[g*4+i][1] + bv;
                r0.z = acc[g*4+i][2] + bv; r0.w = acc[g*4+i][3] + bv;
                r1.x = acc[g*4+i][4] + bv; r1.y = acc[g*4+i][5] + bv;
                r1.z = acc[g*4+i][6] + bv; r1.w = acc[g*4+i][7] + bv;
                *(float4*)(op + tx * 4)      = r0;
                *(float4*)(op + 64 + tx * 4) = r1;
            }
        }
    }
}

// ---------------------------------------------------------------------------
// K4a: per-head denominator, reciprocal:  g_srec = 1 / conv(cexp, rexp)
// grid (WD/1024, HEADS, B), 256 threads, 4 outputs/thread, register window.
// ---------------------------------------------------------------------------
constexpr int CT = 1024;   // outputs per block along w

__global__ __launch_bounds__(256)
void k_sumc(const float* __restrict__ rpe)
{
    __shared__ float sce[CT + 2 * PAD];
    __shared__ float srk[KW];
    int t  = threadIdx.x;
    int h  = blockIdx.y;
    int b  = blockIdx.z;
    int w0 = blockIdx.x * CT;

    if (t < KW) srk[t] = expf(rpe[h * KW + t]);
    const float* ce = g_cexp + ((size_t)(b * HEADS + h)) * WD;
    for (int i = t; i < CT + 2 * PAD; i += 256) {
        int g = w0 - PAD + i;
        sce[i] = (g >= 0 && g < WD) ? ce[g] : 0.f;
    }
    __syncthreads();

    float rk[KW];
    #pragma unroll
    for (int k = 0; k < KW; k++) rk[k] = srk[k];

    int base = t * 4;
    float win[34];
    #pragma unroll
    for (int j = 0; j < 34; j++) win[j] = sce[base + j];

    float s0 = 0.f, s1 = 0.f, s2 = 0.f, s3 = 0.f;
    #pragma unroll
    for (int k = 0; k < KW; k++) {
        float r = rk[k];
        s0 += r * win[k];     s1 += r * win[k + 1];
        s2 += r * win[k + 2]; s3 += r * win[k + 3];
    }
    float4 o;
    o.x = 1.f / s0; o.y = 1.f / s1; o.z = 1.f / s2; o.w = 1.f / s3;
    *(float4*)&g_srec[((size_t)(b * HEADS + h)) * WD + w0 + base] = o;
}

// ---------------------------------------------------------------------------
// K4b: numerator conv + scale:  g_u = conv(vc, rexp) * g_srec
// grid (WD/1024, C, B), 256 threads, 4 outputs/thread, register window.
// ---------------------------------------------------------------------------
__global__ __launch_bounds__(256)
void k_conv(const float* __restrict__ rpe)
{
    __shared__ float svc[CT + 2 * PAD];
    __shared__ float srk[KW];
    int t  = threadIdx.x;
    int c  = blockIdx.y;
    int b  = blockIdx.z;
    int w0 = blockIdx.x * CT;
    int h  = c >> 5;

    if (t < KW) srk[t] = expf(rpe[h * KW + t]);
    const float* vcrow = g_vc + ((size_t)(b * C + c)) * WD;
    for (int i = t; i < CT + 2 * PAD; i += 256) {
        int g = w0 - PAD + i;
        svc[i] = (g >= 0 && g < WD) ? vcrow[g] : 0.f;
    }
    __syncthreads();

    float rk[KW];
    #pragma unroll
    for (int k = 0; k < KW; k++) rk[k] = srk[k];

    int base = t * 4;
    float win[34];
    #pragma unroll
    for (int j = 0; j < 34; j++) win[j] = svc[base + j];

    float s0 = 0.f, s1 = 0.f, s2 = 0.f, s3 = 0.f;
    #pragma unroll
    for (int k = 0; k < KW; k++) {
        float r = rk[k];
        s0 += r * win[k];     s1 += r * win[k + 1];
        s2 += r * win[k + 2]; s3 += r * win[k + 3];
    }
    float4 rec = *(const float4*)&g_srec[((size_t)(b * HEADS + h)) * WD + w0 + base];
    float4 o;
    o.x = s0 * rec.x; o.y = s1 * rec.y; o.z = s2 * rec.z; o.w = s3 * rec.w;
    *(float4*)&g_u[((size_t)(b * C + c)) * WD + w0 + base] = o;
}

// ---------------------------------------------------------------------------
extern "C" void kernel_launch(void* const* d_in, const int* in_sizes, int n_in,
                              void* d_out, int out_size)
{
    (void)in_sizes; (void)n_in; (void)out_size;
    const float* x     = (const float*)d_in[0];
    const float* query = (const float*)d_in[1];
    const float* Wk    = (const float*)d_in[2];
    const float* Wkb   = (const float*)d_in[3];
    const float* rpe   = (const float*)d_in[4];
    const float* Wv    = (const float*)d_in[5];
    const float* bv    = (const float*)d_in[6];
    const float* Wo    = (const float*)d_in[7];
    const float* bo    = (const float*)d_in[8];
    float* out = (float*)d_out;

    k_prep<<<1, 256>>>(query, Wk, Wkb);
    k_cost<<<dim3(WD / 256, Bsz), 256>>>(x);
    k_sumc<<<dim3(WD / CT, HEADS, Bsz), 256>>>(rpe);
    k_gemm<0><<<dim3(WD / BN, C / BM, Bsz), 256>>>(Wv, bv, x, nullptr);
    k_conv<<<dim3(WD / CT, C, Bsz), 256>>>(rpe);
    k_gemm<1><<<dim3(WD / BN, C / BM, Bsz), 256>>>(Wo, bo, nullptr, out);
}

// round 11
// speedup vs baseline: 1.9733x; 1.2088x over previous
#include <cuda_runtime.h>
#include <cuda_bf16.h>
#include <cstdint>
#include <math.h>

#define WD 16384
constexpr int Bsz   = 8;
constexpr int C     = 256;   // CIN == HID
constexpr int HEADS = 8;
constexpr int KW    = 31;
constexpr int PAD   = 15;

// ---- scratch (device globals: allocation-free) ----
__device__ float g_qWk[C * HEADS];
__device__ float g_qb[HEADS];
__device__ float g_cexp[(size_t)Bsz * HEADS * WD];       // 4 MB
__device__ float g_srec[(size_t)Bsz * HEADS * WD];       // 4 MB (1/sum_c)
__device__ float g_vc [(size_t)Bsz * C * WD];            // 128 MB
__device__ float g_u  [(size_t)Bsz * C * WD];            // 128 MB

// ===========================================================================
// portable tensor-core helpers (sm_80-level PTX only; no 'a' features)
// ===========================================================================
__device__ __forceinline__ uint32_t smem_u32(const void* p) {
    uint32_t a;
    asm("{ .reg .u64 t; cvta.to.shared.u64 t, %1; cvt.u32.u64 %0, t; }" : "=r"(a) : "l"(p));
    return a;
}
__device__ __forceinline__ void ldm_x4(uint32_t* r, uint32_t addr) {
    asm volatile("ldmatrix.sync.aligned.m8n8.x4.shared.b16 {%0,%1,%2,%3}, [%4];"
        : "=r"(r[0]), "=r"(r[1]), "=r"(r[2]), "=r"(r[3]) : "r"(addr));
}
__device__ __forceinline__ void mma_bf16(float* d, const uint32_t* a, const uint32_t* b) {
    asm volatile("mma.sync.aligned.m16n8k16.row.col.f32.bf16.bf16.f32 "
        "{%0,%1,%2,%3}, {%4,%5,%6,%7}, {%8,%9}, {%0,%1,%2,%3};"
        : "+f"(d[0]), "+f"(d[1]), "+f"(d[2]), "+f"(d[3])
        : "r"(a[0]), "r"(a[1]), "r"(a[2]), "r"(a[3]), "r"(b[0]), "r"(b[1]));
}
// fp32 pair -> packed bf16x2 (hi) + packed bf16x2 (lo residual)
__device__ __forceinline__ void cvt2(float x, float y, uint32_t& hi, uint32_t& lo) {
    __nv_bfloat16 hx = __float2bfloat16(x), hy = __float2bfloat16(y);
    __nv_bfloat16 lx = __float2bfloat16(x - __bfloat162float(hx));
    __nv_bfloat16 ly = __float2bfloat16(y - __bfloat162float(hy));
    hi = ((uint32_t)*(uint16_t*)&hy << 16) | (uint32_t)*(uint16_t*)&hx;
    lo = ((uint32_t)*(uint16_t*)&ly << 16) | (uint32_t)*(uint16_t*)&lx;
}
// swizzled chunk address: tile rows of 64 bf16 (128 B), 16B chunks XOR-swizzled
__device__ __forceinline__ uint32_t caddr(int row, int u) {
    return (uint32_t)(row * 128 + ((u ^ (row & 7)) << 4));
}

// ===========================================================================
// K1: query prep
// ===========================================================================
__global__ void k_prep(const float* __restrict__ query,
                       const float* __restrict__ Wk,
                       const float* __restrict__ Wk_bias)
{
    __shared__ float qn[C];
    int t = threadIdx.x;
    float qv = query[t];
    float ss = qv * qv;
    #pragma unroll
    for (int o = 16; o > 0; o >>= 1) ss += __shfl_xor_sync(0xffffffffu, ss, o);
    float nrm = sqrtf(ss) + 1e-6f;
    float qnv = (qv / nrm) * 0.17677669529663687f;
    qn[t] = qnv;
    float bb = qnv * Wk_bias[t];
    #pragma unroll
    for (int o = 16; o > 0; o >>= 1) bb += __shfl_xor_sync(0xffffffffu, bb, o);
    if ((t & 31) == 0) g_qb[t >> 5] = bb;
    __syncthreads();
    #pragma unroll
    for (int h = 0; h < HEADS; h++) {
        float acc = 0.f;
        #pragma unroll
        for (int e = 0; e < 32; e++)
            acc += qn[h * 32 + e] * Wk[t * C + h * 32 + e];
        g_qWk[t * HEADS + h] = acc;
    }
}

// ===========================================================================
// K2: cost_exp
// ===========================================================================
__global__ __launch_bounds__(256)
void k_cost(const float* __restrict__ x)
{
    __shared__ float sQ[C * HEADS];
    __shared__ float sqb[HEADS];
    int t = threadIdx.x;
    for (int i = t; i < C * HEADS; i += 256) sQ[i] = g_qWk[i];
    if (t < HEADS) sqb[t] = g_qb[t];
    __syncthreads();

    int b = blockIdx.y;
    int w = blockIdx.x * 256 + t;
    const float* xp = x + ((size_t)b * C) * WD + w;

    float acc[HEADS];
    #pragma unroll
    for (int h = 0; h < HEADS; h++) acc[h] = sqb[h];
    for (int d = 0; d < C; d++) {
        float xv = xp[(size_t)d * WD];
        #pragma unroll
        for (int h = 0; h < HEADS; h++) acc[h] += xv * sQ[d * HEADS + h];
    }
    #pragma unroll
    for (int h = 0; h < HEADS; h++)
        g_cexp[((size_t)(b * HEADS + h)) * WD + w] = expf(acc[h]);
}

// ===========================================================================
// mma.sync split-bf16 GEMM: Out[b][o][w] = sum_d Wt[o][d] * In[b][d][w]
// CTA tile 128(o) x 128(w), K chunks of 64, 3 passes: AhiBhi + AhiBlo + AloBhi
// 8 warps: 4 along M x 2 along N; warp tile 32x64.
// MODE 0: In = x, Out = g_vc, epilogue (acc+bias)*cexp
// MODE 1: In = g_u, Out = param, epilogue acc+bias
// ===========================================================================
constexpr int KC    = 64;
constexpr int TILEB = 128 * KC * 2;          // 16384 B per operand buffer
constexpr int OF_AHI = 0;
constexpr int OF_ALO = OF_AHI + TILEB;
constexpr int OF_BHI = OF_ALO + TILEB;
constexpr int OF_BLO = OF_BHI + TILEB;
constexpr int GSMEM  = OF_BLO + TILEB;       // 65536 B

template <int MODE>
__global__ __launch_bounds__(256, 2)
void k_mma_gemm(const float* __restrict__ Wt,
                const float* __restrict__ bias,
                const float* __restrict__ InP,
                float* __restrict__ OutP)
{
    extern __shared__ char smem[];
    uint32_t sb = smem_u32(smem);
    int t   = threadIdx.x;
    int wid = t >> 5;
    int lid = t & 31;
    int b   = blockIdx.z;
    int o0  = blockIdx.y * 128;
    int w0  = blockIdx.x * 128;

    const float* In  = (MODE == 0) ? InP : g_u;
    float*       Out = (MODE == 0) ? g_vc : OutP;

    int wm = (wid >> 1) * 32;     // warp M offset
    int wn = (wid & 1) * 64;      // warp N offset

    float acc[2][8][4];
    #pragma unroll
    for (int f = 0; f < 2; f++)
        #pragma unroll
        for (int nf = 0; nf < 8; nf++)
            #pragma unroll
            for (int i = 0; i < 4; i++) acc[f][nf][i] = 0.f;

    // lane-derived ldmatrix row/u offsets
    int a_r  = lid & 15;              // + frag*16 + wm
    int a_u  = lid >> 4;              // + 2*kstep
    int b_r  = (lid & 7) + ((lid >> 4) << 3);   // + pair*16 + wn
    int b_u  = (lid >> 3) & 1;        // + 2*kstep

    for (int k0 = 0; k0 < C; k0 += KC) {
        // ---- convert A: Wt[o0+m][k0+k] -> Ahi/Alo ----
        #pragma unroll
        for (int j = 0; j < 4; j++) {
            int idx = t + 256 * j;
            int m = idx >> 3;
            int u = idx & 7;
            const float* ap = Wt + (size_t)(o0 + m) * C + k0 + u * 8;
            float4 a0 = *(const float4*)ap;
            float4 a1 = *(const float4*)(ap + 4);
            uint32_t h[4], l[4];
            cvt2(a0.x, a0.y, h[0], l[0]); cvt2(a0.z, a0.w, h[1], l[1]);
            cvt2(a1.x, a1.y, h[2], l[2]); cvt2(a1.z, a1.w, h[3], l[3]);
            uint32_t ca = caddr(m, u);
            asm volatile("st.shared.v4.b32 [%0], {%1,%2,%3,%4};"
                         :: "r"(sb + OF_AHI + ca), "r"(h[0]), "r"(h[1]), "r"(h[2]), "r"(h[3]) : "memory");
            asm volatile("st.shared.v4.b32 [%0], {%1,%2,%3,%4};"
                         :: "r"(sb + OF_ALO + ca), "r"(l[0]), "r"(l[1]), "r"(l[2]), "r"(l[3]) : "memory");
        }
        // ---- convert B (transpose): In[k0+k][w0+n] -> B[n][k] ----
        #pragma unroll
        for (int j = 0; j < 4; j++) {
            int idx = t + 256 * j;
            int n = idx & 127;
            int u = idx >> 7;         // 0..7
            const float* bp = In + ((size_t)(b * C + k0 + u * 8)) * WD + w0 + n;
            float v[8];
            #pragma unroll
            for (int i = 0; i < 8; i++) v[i] = bp[(size_t)i * WD];
            uint32_t h[4], l[4];
            cvt2(v[0], v[1], h[0], l[0]); cvt2(v[2], v[3], h[1], l[1]);
            cvt2(v[4], v[5], h[2], l[2]); cvt2(v[6], v[7], h[3], l[3]);
            uint32_t ca = caddr(n, u);
            asm volatile("st.shared.v4.b32 [%0], {%1,%2,%3,%4};"
                         :: "r"(sb + OF_BHI + ca), "r"(h[0]), "r"(h[1]), "r"(h[2]), "r"(h[3]) : "memory");
            asm volatile("st.shared.v4.b32 [%0], {%1,%2,%3,%4};"
                         :: "r"(sb + OF_BLO + ca), "r"(l[0]), "r"(l[1]), "r"(l[2]), "r"(l[3]) : "memory");
        }
        __syncthreads();

        // ---- MMA: 3 passes x 4 k-steps x (2 A-frags x 8 N-frags) ----
        #pragma unroll
        for (int pass = 0; pass < 3; pass++) {
            uint32_t abase = sb + ((pass == 2) ? OF_ALO : OF_AHI);
            uint32_t bbase = sb + ((pass == 1) ? OF_BLO : OF_BHI);
            #pragma unroll
            for (int ks = 0; ks < 4; ks++) {
                int ub = ks * 2;
                uint32_t afrag[2][4];
                #pragma unroll
                for (int f = 0; f < 2; f++)
                    ldm_x4(afrag[f], abase + caddr(wm + f * 16 + a_r, ub + a_u));
                uint32_t bfrag[16];
                #pragma unroll
                for (int p = 0; p < 4; p++)
                    ldm_x4(bfrag + 4 * p, bbase + caddr(wn + p * 16 + b_r, ub + b_u));
                #pragma unroll
                for (int f = 0; f < 2; f++)
                    #pragma unroll
                    for (int nf = 0; nf < 8; nf++)
                        mma_bf16(acc[f][nf], afrag[f], bfrag + 2 * nf);
            }
        }
        __syncthreads();
    }

    // ---- epilogue: fragment-direct stores (float2 = 8B sector-friendly) ----
    #pragma unroll
    for (int f = 0; f < 2; f++) {
        int rbase = wm + f * 16;
        int h = (o0 + rbase) >> 5;
        const float* ce = g_cexp + ((size_t)(b * HEADS + h)) * WD + w0;
        #pragma unroll
        for (int half = 0; half < 2; half++) {
            int o = o0 + rbase + (lid >> 2) + half * 8;
            float bvv = bias[o];
            float* op = Out + ((size_t)(b * C + o)) * WD + w0;
            #pragma unroll
            for (int nf = 0; nf < 8; nf++) {
                int wc = wn + nf * 8 + (lid & 3) * 2;
                float vx = acc[f][nf][half * 2 + 0];
                float vy = acc[f][nf][half * 2 + 1];
                float2 r;
                if (MODE == 0) {
                    float2 c = *(const float2*)(ce + wc);
                    r.x = (vx + bvv) * c.x;
                    r.y = (vy + bvv) * c.y;
                } else {
                    r.x = vx + bvv;
                    r.y = vy + bvv;
                }
                *(float2*)(op + wc) = r;
            }
        }
    }
}

// ===========================================================================
// K4a: denominator reciprocal
// ===========================================================================
constexpr int CT = 1024;

__global__ __launch_bounds__(256)
void k_sumc(const float* __restrict__ rpe)
{
    __shared__ float sce[CT + 2 * PAD];
    __shared__ float srk[KW];
    int t  = threadIdx.x;
    int h  = blockIdx.y;
    int b  = blockIdx.z;
    int w0 = blockIdx.x * CT;

    if (t < KW) srk[t] = expf(rpe[h * KW + t]);
    const float* ce = g_cexp + ((size_t)(b * HEADS + h)) * WD;
    for (int i = t; i < CT + 2 * PAD; i += 256) {
        int g = w0 - PAD + i;
        sce[i] = (g >= 0 && g < WD) ? ce[g] : 0.f;
    }
    __syncthreads();

    float rk[KW];
    #pragma unroll
    for (int k = 0; k < KW; k++) rk[k] = srk[k];

    int base = t * 4;
    float win[34];
    #pragma unroll
    for (int j = 0; j < 34; j++) win[j] = sce[base + j];

    float s0 = 0.f, s1 = 0.f, s2 = 0.f, s3 = 0.f;
    #pragma unroll
    for (int k = 0; k < KW; k++) {
        float r = rk[k];
        s0 += r * win[k];     s1 += r * win[k + 1];
        s2 += r * win[k + 2]; s3 += r * win[k + 3];
    }
    float4 o;
    o.x = 1.f / s0; o.y = 1.f / s1; o.z = 1.f / s2; o.w = 1.f / s3;
    *(float4*)&g_srec[((size_t)(b * HEADS + h)) * WD + w0 + base] = o;
}

// ===========================================================================
// K4b: numerator conv + scale
// ===========================================================================
__global__ __launch_bounds__(256)
void k_conv(const float* __restrict__ rpe)
{
    __shared__ float svc[CT + 2 * PAD];
    __shared__ float srk[KW];
    int t  = threadIdx.x;
    int c  = blockIdx.y;
    int b  = blockIdx.z;
    int w0 = blockIdx.x * CT;
    int h  = c >> 5;

    if (t < KW) srk[t] = expf(rpe[h * KW + t]);
    const float* vcrow = g_vc + ((size_t)(b * C + c)) * WD;
    for (int i = t; i < CT + 2 * PAD; i += 256) {
        int g = w0 - PAD + i;
        svc[i] = (g >= 0 && g < WD) ? vcrow[g] : 0.f;
    }
    __syncthreads();

    float rk[KW];
    #pragma unroll
    for (int k = 0; k < KW; k++) rk[k] = srk[k];

    int base = t * 4;
    float win[34];
    #pragma unroll
    for (int j = 0; j < 34; j++) win[j] = svc[base + j];

    float s0 = 0.f, s1 = 0.f, s2 = 0.f, s3 = 0.f;
    #pragma unroll
    for (int k = 0; k < KW; k++) {
        float r = rk[k];
        s0 += r * win[k];     s1 += r * win[k + 1];
        s2 += r * win[k + 2]; s3 += r * win[k + 3];
    }
    float4 rec = *(const float4*)&g_srec[((size_t)(b * HEADS + h)) * WD + w0 + base];
    float4 o;
    o.x = s0 * rec.x; o.y = s1 * rec.y; o.z = s2 * rec.z; o.w = s3 * rec.w;
    *(float4*)&g_u[((size_t)(b * C + c)) * WD + w0 + base] = o;
}

// ===========================================================================
extern "C" void kernel_launch(void* const* d_in, const int* in_sizes, int n_in,
                              void* d_out, int out_size)
{
    (void)in_sizes; (void)n_in; (void)out_size;
    const float* x     = (const float*)d_in[0];
    const float* query = (const float*)d_in[1];
    const float* Wk    = (const float*)d_in[2];
    const float* Wkb   = (const float*)d_in[3];
    const float* rpe   = (const float*)d_in[4];
    const float* Wv    = (const float*)d_in[5];
    const float* bv    = (const float*)d_in[6];
    const float* Wo    = (const float*)d_in[7];
    const float* bo    = (const float*)d_in[8];
    float* out = (float*)d_out;

    cudaFuncSetAttribute(k_mma_gemm<0>, cudaFuncAttributeMaxDynamicSharedMemorySize, GSMEM);
    cudaFuncSetAttribute(k_mma_gemm<1>, cudaFuncAttributeMaxDynamicSharedMemorySize, GSMEM);

    k_prep<<<1, 256>>>(query, Wk, Wkb);
    k_cost<<<dim3(WD / 256, Bsz), 256>>>(x);
    k_sumc<<<dim3(WD / CT, HEADS, Bsz), 256>>>(rpe);
    k_mma_gemm<0><<<dim3(WD / 128, C / 128, Bsz), 256, GSMEM>>>(Wv, bv, x, nullptr);
    k_conv<<<dim3(WD / CT, C, Bsz), 256>>>(rpe);
    k_mma_gemm<1><<<dim3(WD / 128, C / 128, Bsz), 256, GSMEM>>>(Wo, bo, nullptr, out);
}

// round 13
// speedup vs baseline: 2.8285x; 1.4334x over previous
#include <cuda_runtime.h>
#include <cuda_bf16.h>
#include <cstdint>
#include <math.h>

#define WD 16384
constexpr int Bsz   = 8;
constexpr int C     = 256;   // CIN == HID
constexpr int HEADS = 8;
constexpr int KW    = 31;
constexpr int PAD   = 15;

// ---- scratch (device globals: allocation-free) ----
__device__ float g_qWk[C * HEADS];
__device__ float g_qb[HEADS];
__device__ float g_cexp[(size_t)Bsz * HEADS * WD];       // 4 MB
__device__ float g_srec[(size_t)Bsz * HEADS * WD];       // 4 MB (1/sum_c)
__device__ float g_vc [(size_t)Bsz * C * WD];            // 128 MB
// pre-split bf16 operand planes
__device__ __nv_bfloat16 g_xhi[(size_t)Bsz * C * WD];    // 64 MB
__device__ __nv_bfloat16 g_xlo[(size_t)Bsz * C * WD];    // 64 MB
__device__ __nv_bfloat16 g_uhi[(size_t)Bsz * C * WD];    // 64 MB
__device__ __nv_bfloat16 g_ulo[(size_t)Bsz * C * WD];    // 64 MB
__device__ __nv_bfloat16 g_wvhi[C * C], g_wvlo[C * C];
__device__ __nv_bfloat16 g_wohi[C * C], g_wolo[C * C];

// ===========================================================================
// portable PTX helpers (sm_80-level only; no 'a' features)
// ===========================================================================
__device__ __forceinline__ uint32_t smem_u32(const void* p) {
    uint32_t a;
    asm("{ .reg .u64 t; cvta.to.shared.u64 t, %1; cvt.u32.u64 %0, t; }" : "=r"(a) : "l"(p));
    return a;
}
__device__ __forceinline__ void ldm_x4(uint32_t* r, uint32_t addr) {
    asm volatile("ldmatrix.sync.aligned.m8n8.x4.shared.b16 {%0,%1,%2,%3}, [%4];"
        : "=r"(r[0]), "=r"(r[1]), "=r"(r[2]), "=r"(r[3]) : "r"(addr));
}
__device__ __forceinline__ void ldm_x4_t(uint32_t* r, uint32_t addr) {
    asm volatile("ldmatrix.sync.aligned.m8n8.x4.trans.shared.b16 {%0,%1,%2,%3}, [%4];"
        : "=r"(r[0]), "=r"(r[1]), "=r"(r[2]), "=r"(r[3]) : "r"(addr));
}
__device__ __forceinline__ void mma_bf16(float* d, const uint32_t* a, const uint32_t* b) {
    asm volatile("mma.sync.aligned.m16n8k16.row.col.f32.bf16.bf16.f32 "
        "{%0,%1,%2,%3}, {%4,%5,%6,%7}, {%8,%9}, {%0,%1,%2,%3};"
        : "+f"(d[0]), "+f"(d[1]), "+f"(d[2]), "+f"(d[3])
        : "r"(a[0]), "r"(a[1]), "r"(a[2]), "r"(a[3]), "r"(b[0]), "r"(b[1]));
}
#define CP16(dst, src) asm volatile("cp.async.cg.shared.global [%0], [%1], 16;" :: "r"(dst), "l"(src) : "memory")
#define CP_COMMIT()    asm volatile("cp.async.commit_group;" ::: "memory")
#define CP_WAIT(n)     asm volatile("cp.async.wait_group %0;" :: "n"(n) : "memory")

__device__ __forceinline__ void split2(float v, __nv_bfloat16& h, __nv_bfloat16& l) {
    h = __float2bfloat16(v);
    l = __float2bfloat16(v - __bfloat162float(h));
}

// ===========================================================================
// K1: query prep
// ===========================================================================
__global__ void k_prep(const float* __restrict__ query,
                       const float* __restrict__ Wk,
                       const float* __restrict__ Wk_bias)
{
    __shared__ float qn[C];
    int t = threadIdx.x;
    float qv = query[t];
    float ss = qv * qv;
    #pragma unroll
    for (int o = 16; o > 0; o >>= 1) ss += __shfl_xor_sync(0xffffffffu, ss, o);
    float nrm = sqrtf(ss) + 1e-6f;
    float qnv = (qv / nrm) * 0.17677669529663687f;
    qn[t] = qnv;
    float bb = qnv * Wk_bias[t];
    #pragma unroll
    for (int o = 16; o > 0; o >>= 1) bb += __shfl_xor_sync(0xffffffffu, bb, o);
    if ((t & 31) == 0) g_qb[t >> 5] = bb;
    __syncthreads();
    #pragma unroll
    for (int h = 0; h < HEADS; h++) {
        float acc = 0.f;
        #pragma unroll
        for (int e = 0; e < 32; e++)
            acc += qn[h * 32 + e] * Wk[t * C + h * 32 + e];
        g_qWk[t * HEADS + h] = acc;
    }
}

// ===========================================================================
// K1b: weight split (both matrices)
// ===========================================================================
__global__ void k_wcvt(const float* __restrict__ Wv, const float* __restrict__ Wo)
{
    int i = blockIdx.x * 256 + threadIdx.x;   // 0..65535
    split2(Wv[i], g_wvhi[i], g_wvlo[i]);
    split2(Wo[i], g_wohi[i], g_wolo[i]);
}

// ===========================================================================
// K2: cost_exp + x split (fused: single pass over x)
// ===========================================================================
__global__ __launch_bounds__(256)
void k_cost(const float* __restrict__ x)
{
    __shared__ float sQ[C * HEADS];
    __shared__ float sqb[HEADS];
    int t = threadIdx.x;
    for (int i = t; i < C * HEADS; i += 256) sQ[i] = g_qWk[i];
    if (t < HEADS) sqb[t] = g_qb[t];
    __syncthreads();

    int b = blockIdx.y;
    int w = blockIdx.x * 256 + t;
    size_t bC = (size_t)b * C;
    const float* xp = x + bC * WD + w;

    float acc[HEADS];
    #pragma unroll
    for (int h = 0; h < HEADS; h++) acc[h] = sqb[h];
    for (int d = 0; d < C; d++) {
        float xv = xp[(size_t)d * WD];
        __nv_bfloat16 hh, ll;
        split2(xv, hh, ll);
        size_t off = (bC + d) * WD + w;
        g_xhi[off] = hh;
        g_xlo[off] = ll;
        #pragma unroll
        for (int h = 0; h < HEADS; h++) acc[h] += xv * sQ[d * HEADS + h];
    }
    #pragma unroll
    for (int h = 0; h < HEADS; h++)
        g_cexp[((size_t)(b * HEADS + h)) * WD + w] = expf(acc[h]);
}

// ===========================================================================
// cp.async pipelined split-bf16 mma.sync GEMM
// Out[b][o][w] = sum_d W[o][d] * In[b][d][w]   (3 passes: HH + LH + HL)
// CTA tile 128(o) x 128(w), K chunks of 32, 2-stage pipeline.
// 8 warps: 4 along M x 2 along N; warp tile 32x64.
// smem per stage: A (hi|lo interleaved, rows 128B) 16KB + Bhi 8KB + Blo 8KB
// MODE 0: B = xhi/xlo, Out = g_vc, epilogue (acc+bias)*cexp
// MODE 1: B = uhi/ulo, Out = param, epilogue acc+bias
// ===========================================================================
constexpr int KC    = 32;
constexpr int OF_A  = 0;
constexpr int OF_BH = 16384;
constexpr int OF_BL = 24576;
constexpr int STAGE = 32768;
constexpr int GSMEM = 2 * STAGE;     // 65536

template <int MODE>
__global__ __launch_bounds__(256, 2)
void k_mma_gemm(const float* __restrict__ bias, float* __restrict__ OutP)
{
    extern __shared__ char smem[];
    uint32_t sb = smem_u32(smem);
    int t   = threadIdx.x;
    int wid = t >> 5;
    int lid = t & 31;
    int b   = blockIdx.z;
    int o0  = blockIdx.y * 128;
    int w0  = blockIdx.x * 128;
    size_t bC = (size_t)b * C;

    const __nv_bfloat16* whi = (MODE == 0) ? g_wvhi : g_wohi;
    const __nv_bfloat16* wlo = (MODE == 0) ? g_wvlo : g_wolo;
    const __nv_bfloat16* bhi = (MODE == 0) ? g_xhi : g_uhi;
    const __nv_bfloat16* blo = (MODE == 0) ? g_xlo : g_ulo;
    float* Out = (MODE == 0) ? g_vc : OutP;

    int wm = (wid >> 1) * 32;
    int wn = (wid & 1) * 64;

    float acc[2][8][4];
    #pragma unroll
    for (int f = 0; f < 2; f++)
        #pragma unroll
        for (int nf = 0; nf < 8; nf++)
            #pragma unroll
            for (int i = 0; i < 4; i++) acc[f][nf][i] = 0.f;

    auto load_chunk = [&](int k0, int stg) {
        uint32_t base = sb + stg * STAGE;
        // A: hi chunks 0-3, lo chunks 4-7; row = 128 B
        #pragma unroll
        for (int j = 0; j < 4; j++) {
            int l = t + 256 * j;          // 0..1023
            int row = l >> 3;
            int c = l & 7;
            const __nv_bfloat16* src = ((c < 4) ? whi : wlo)
                                       + (size_t)(o0 + row) * C + k0 + (c & 3) * 8;
            CP16(base + OF_A + row * 128 + ((c ^ (row & 7)) << 4), src);
        }
        // B: [k][n] rows of 256 B
        #pragma unroll
        for (int j = 0; j < 2; j++) {
            int l = t + 256 * j;          // 0..511
            int row = l >> 4;
            int cc = l & 15;
            size_t goff = (bC + k0 + row) * WD + w0 + cc * 8;
            uint32_t sw = row * 256 + ((cc ^ (row & 7)) << 4);
            CP16(base + OF_BH + sw, bhi + goff);
            CP16(base + OF_BL + sw, blo + goff);
        }
    };

    load_chunk(0, 0);
    CP_COMMIT();

    for (int c = 0; c < 8; c++) {
        if (c < 7) { load_chunk((c + 1) * KC, (c + 1) & 1); CP_COMMIT(); CP_WAIT(1); }
        else       { CP_WAIT(0); }
        __syncthreads();

        uint32_t Ab = sb + (c & 1) * STAGE + OF_A;
        uint32_t BH = sb + (c & 1) * STAGE + OF_BH;
        uint32_t BL = sb + (c & 1) * STAGE + OF_BL;

        #pragma unroll
        for (int ks = 0; ks < 2; ks++) {
            // A frags (hi + lo)
            uint32_t ah[2][4], al[2][4];
            #pragma unroll
            for (int f = 0; f < 2; f++) {
                int r  = wm + f * 16 + (lid & 15);
                int kc = 2 * ks + (lid >> 4);
                ldm_x4(ah[f], Ab + r * 128 + ((kc ^ (r & 7)) << 4));
                ldm_x4(al[f], Ab + r * 128 + (((kc + 4) ^ (r & 7)) << 4));
            }
            // B hi frags (trans ldmatrix on [k][n])
            int m    = lid >> 3;                      // matrix id 0..3
            int krow = ks * 16 + (m & 1) * 8 + (lid & 7);
            int ccb  = (wn >> 3) + (m >> 1);
            uint32_t bh[16];
            #pragma unroll
            for (int p = 0; p < 4; p++) {
                int cc = ccb + 2 * p;
                ldm_x4_t(bh + 4 * p, BH + krow * 256 + ((cc ^ (krow & 7)) << 4));
            }
            #pragma unroll
            for (int f = 0; f < 2; f++)
                #pragma unroll
                for (int nf = 0; nf < 8; nf++) {
                    mma_bf16(acc[f][nf], ah[f], bh + 2 * nf);
                    mma_bf16(acc[f][nf], al[f], bh + 2 * nf);
                }
            // B lo frags
            uint32_t bl[16];
            #pragma unroll
            for (int p = 0; p < 4; p++) {
                int cc = ccb + 2 * p;
                ldm_x4_t(bl + 4 * p, BL + krow * 256 + ((cc ^ (krow & 7)) << 4));
            }
            #pragma unroll
            for (int f = 0; f < 2; f++)
                #pragma unroll
                for (int nf = 0; nf < 8; nf++)
                    mma_bf16(acc[f][nf], ah[f], bl + 2 * nf);
        }
        __syncthreads();
    }

    // ---- epilogue: fragment-direct float2 stores ----
    #pragma unroll
    for (int f = 0; f < 2; f++) {
        int rbase = wm + f * 16;
        int h = (o0 + rbase) >> 5;
        const float* ce = g_cexp + ((size_t)(b * HEADS + h)) * WD + w0;
        #pragma unroll
        for (int half = 0; half < 2; half++) {
            int o = o0 + rbase + (lid >> 2) + half * 8;
            float bvv = bias[o];
            float* op = Out + (bC + o) * WD + w0;
            #pragma unroll
            for (int nf = 0; nf < 8; nf++) {
                int wc = wn + nf * 8 + (lid & 3) * 2;
                float vx = acc[f][nf][half * 2 + 0];
                float vy = acc[f][nf][half * 2 + 1];
                float2 r;
                if (MODE == 0) {
                    float2 cc = *(const float2*)(ce + wc);
                    r.x = (vx + bvv) * cc.x;
                    r.y = (vy + bvv) * cc.y;
                } else {
                    r.x = vx + bvv;
                    r.y = vy + bvv;
                }
                *(float2*)(op + wc) = r;
            }
        }
    }
}

// ===========================================================================
// K4a: denominator reciprocal
// ===========================================================================
constexpr int CT = 1024;

__global__ __launch_bounds__(256)
void k_sumc(const float* __restrict__ rpe)
{
    __shared__ float sce[CT + 2 * PAD];
    __shared__ float srk[KW];
    int t  = threadIdx.x;
    int h  = blockIdx.y;
    int b  = blockIdx.z;
    int w0 = blockIdx.x * CT;

    if (t < KW) srk[t] = expf(rpe[h * KW + t]);
    const float* ce = g_cexp + ((size_t)(b * HEADS + h)) * WD;
    for (int i = t; i < CT + 2 * PAD; i += 256) {
        int g = w0 - PAD + i;
        sce[i] = (g >= 0 && g < WD) ? ce[g] : 0.f;
    }
    __syncthreads();

    float rk[KW];
    #pragma unroll
    for (int k = 0; k < KW; k++) rk[k] = srk[k];

    int base = t * 4;
    float win[34];
    #pragma unroll
    for (int j = 0; j < 34; j++) win[j] = sce[base + j];

    float s0 = 0.f, s1 = 0.f, s2 = 0.f, s3 = 0.f;
    #pragma unroll
    for (int k = 0; k < KW; k++) {
        float r = rk[k];
        s0 += r * win[k];     s1 += r * win[k + 1];
        s2 += r * win[k + 2]; s3 += r * win[k + 3];
    }
    float4 o;
    o.x = 1.f / s0; o.y = 1.f / s1; o.z = 1.f / s2; o.w = 1.f / s3;
    *(float4*)&g_srec[((size_t)(b * HEADS + h)) * WD + w0 + base] = o;
}

// ===========================================================================
// K4b: numerator conv + scale -> u split directly to bf16 hi/lo
// ===========================================================================
__global__ __launch_bounds__(256)
void k_conv(const float* __restrict__ rpe)
{
    __shared__ float svc[CT + 2 * PAD];
    __shared__ float srk[KW];
    int t  = threadIdx.x;
    int c  = blockIdx.y;
    int b  = blockIdx.z;
    int w0 = blockIdx.x * CT;
    int h  = c >> 5;

    if (t < KW) srk[t] = expf(rpe[h * KW + t]);
    const float* vcrow = g_vc + ((size_t)(b * C + c)) * WD;
    for (int i = t; i < CT + 2 * PAD; i += 256) {
        int g = w0 - PAD + i;
        svc[i] = (g >= 0 && g < WD) ? vcrow[g] : 0.f;
    }
    __syncthreads();

    float rk[KW];
    #pragma unroll
    for (int k = 0; k < KW; k++) rk[k] = srk[k];

    int base = t * 4;
    float win[34];
    #pragma unroll
    for (int j = 0; j < 34; j++) win[j] = svc[base + j];

    float s0 = 0.f, s1 = 0.f, s2 = 0.f, s3 = 0.f;
    #pragma unroll
    for (int k = 0; k < KW; k++) {
        float r = rk[k];
        s0 += r * win[k];     s1 += r * win[k + 1];
        s2 += r * win[k + 2]; s3 += r * win[k + 3];
    }
    float4 rec = *(const float4*)&g_srec[((size_t)(b * HEADS + h)) * WD + w0 + base];
    float u[4] = { s0 * rec.x, s1 * rec.y, s2 * rec.z, s3 * rec.w };

    size_t off = ((size_t)(b * C + c)) * WD + w0 + base;
    __nv_bfloat16 hh[4], ll[4];
    #pragma unroll
    for (int i = 0; i < 4; i++) split2(u[i], hh[i], ll[i]);
    *(uint2*)&g_uhi[off] = *(uint2*)hh;   // 4 x bf16 = 8 B
    *(uint2*)&g_ulo[off] = *(uint2*)ll;
}

// ===========================================================================
extern "C" void kernel_launch(void* const* d_in, const int* in_sizes, int n_in,
                              void* d_out, int out_size)
{
    (void)in_sizes; (void)n_in; (void)out_size;
    const float* x     = (const float*)d_in[0];
    const float* query = (const float*)d_in[1];
    const float* Wk    = (const float*)d_in[2];
    const float* Wkb   = (const float*)d_in[3];
    const float* rpe   = (const float*)d_in[4];
    const float* Wv    = (const float*)d_in[5];
    const float* bv    = (const float*)d_in[6];
    const float* Wo    = (const float*)d_in[7];
    const float* bo    = (const float*)d_in[8];
    float* out = (float*)d_out;

    cudaFuncSetAttribute(k_mma_gemm<0>, cudaFuncAttributeMaxDynamicSharedMemorySize, GSMEM);
    cudaFuncSetAttribute(k_mma_gemm<1>, cudaFuncAttributeMaxDynamicSharedMemorySize, GSMEM);

    k_prep<<<1, 256>>>(query, Wk, Wkb);
    k_wcvt<<<C * C / 256, 256>>>(Wv, Wo);
    k_cost<<<dim3(WD / 256, Bsz), 256>>>(x);
    k_sumc<<<dim3(WD / CT, HEADS, Bsz), 256>>>(rpe);
    k_mma_gemm<0><<<dim3(WD / 128, C / 128, Bsz), 256, GSMEM>>>(bv, nullptr);
    k_conv<<<dim3(WD / CT, C, Bsz), 256>>>(rpe);
    k_mma_gemm<1><<<dim3(WD / 128, C / 128, Bsz), 256, GSMEM>>>(bo, out);
}